// round 11
// baseline (speedup 1.0000x reference)
#include <cuda_runtime.h>

// ConvCapsMatrix: EM-routing matrix capsules, fully fused.
// B=4, 14x14 -> 12x12, KH=KW=3, IC=OC=32, M=4 (P=16), ITERS=3.
//
// R10 -> R11: still latency-bound (issue 43.7%, fma 49.6%).
//  (a) 128-thread CTAs, __launch_bounds__(128,4): FOUR independent CTAs/SM
//      at the same 16 warps / 128 regs; grid 576 <= 148*4 -> single wave.
//  (b) logp via expanded quadratic: s = PRE - (sum v^2*h + sum v*hm2) with
//      hm2 = -mu/sig2 and the constants (C = sum mu^2*h, 0.5*sum log sig2,
//      log a_out) all folded into one per-o PRE -> two parallel FMA chains
//      instead of one serial d/d^2 chain.
// History: R6 W transpose 229.6->162.3; R9 reg-hoist ->139.3; R10 (256,2)
// + redux-max ->121.3.
//
// Roles in a 128-thread CTA (one CTA per output position):
//  streaming: (nn = warp 0..3, o = lane 0..31); 72 chunks per warp
//  stats:     (o = (tid>>4) + 8k, p = tid&15), k = 0..3

#define NPOS  576           // 4 * 12 * 12
#define EPSF  1e-8f

// dynamic smem layout (float offsets)
#define SM_XP    0          // [4608]  x patch [n][p]
#define SM_A     4608       // [288]   a patch
#define SM_HM2   4896       // [576]   -mu/sig2, [o*18+p] (u64-pair readable)
#define SM_HSG   5472       // [576]   0.5/sig2, same layout
#define SM_PRE   6048       // [32]    log(a_out)-0.5*sum log sig2 - sum mu^2*h
#define SM_RED1  6080       // [4*544] per-warp S1 partials [w*544+o*17+p], p=16 -> Rs
#define SM_RED2  8256       // [4*544] per-warp S2 partials
#define SM_TOT   10432      // floats -> 41728 bytes (x4 CTAs = 167KB/SM)

typedef unsigned long long u64;

// transposed W: ulonglong2[(n*4+y)*32 + o] = W[n][o][y][0..3]  (576 KB scratch)
__device__ ulonglong2 g_Wt[288 * 4 * 32];

__device__ __forceinline__ u64 pk2(float lo, float hi) {
    u64 r; asm("mov.b64 %0, {%1, %2};" : "=l"(r) : "f"(lo), "f"(hi)); return r;
}
__device__ __forceinline__ void upk2(u64 v, float& lo, float& hi) {
    asm("mov.b64 {%0, %1}, %2;" : "=f"(lo), "=f"(hi) : "l"(v));
}
__device__ __forceinline__ u64 fma2(u64 a, u64 b, u64 c) {
    u64 d; asm("fma.rn.f32x2 %0, %1, %2, %3;" : "=l"(d) : "l"(a), "l"(b), "l"(c)); return d;
}
__device__ __forceinline__ u64 mul2(u64 a, u64 b) {
    u64 d; asm("mul.rn.f32x2 %0, %1, %2;" : "=l"(d) : "l"(a), "l"(b)); return d;
}
__device__ __forceinline__ u64 add2(u64 a, u64 b) {
    u64 d; asm("add.rn.f32x2 %0, %1, %2;" : "=l"(d) : "l"(a), "l"(b)); return d;
}
// warp-max of a float via integer redux (monotone order-preserving key)
__device__ __forceinline__ float warp_max_f32(float s) {
    unsigned sb = __float_as_uint(s);
    unsigned key = sb ^ ((unsigned)(((int)sb) >> 31) | 0x80000000u);
    unsigned mk;
    asm("redux.sync.max.u32 %0, %1, 0xffffffff;" : "=r"(mk) : "r"(key));
    unsigned mb = mk ^ ((unsigned)(((int)(~mk)) >> 31) | 0x80000000u);
    return __uint_as_float(mb);
}

__global__ void __launch_bounds__(256)
transpose_W_kernel(const float4* __restrict__ W4)
{
    int idx = blockIdx.x * 256 + threadIdx.x;   // (n*4+y)*32 + o
    if (idx >= 288 * 4 * 32) return;
    int o  = idx & 31;
    int ny = idx >> 5;
    int y  = ny & 3;
    int n  = ny >> 2;
    float4 r = W4[(n * 32 + o) * 4 + y];
    ulonglong2 v;
    v.x = pk2(r.x, r.y);
    v.y = pk2(r.z, r.w);
    g_Wt[idx] = v;                               // coalesced 16B store
}

extern __shared__ float smem[];

__global__ void __launch_bounds__(128, 4)
caps_kernel(const float* __restrict__ x, const float* __restrict__ a,
            const float* __restrict__ bu_g, const float* __restrict__ ba_g,
            float* __restrict__ out)
{
    const int tid = threadIdx.x;
    const int pos = blockIdx.x;
    const int b  = pos / 144;
    const int hw = pos - b * 144;
    const int h  = hw / 12;
    const int w  = hw - h * 12;

    // ---- load x / a patches into smem (coalesced) ----
    for (int idx = tid; idx < 4608; idx += 128) {
        int n = idx >> 4, q = idx & 15;
        int k = n / 96;
        int r = n - k * 96;
        int l = r >> 5;
        int c = r & 31;
        smem[SM_XP + idx] = x[(((b * 14 + h + k) * 14 + (w + l)) * 32 + c) * 16 + q];
    }
    for (int n = tid; n < 288; n += 128) {
        int k = n / 96;
        int r = n - k * 96;
        int l = r >> 5;
        int c = r & 31;
        smem[SM_A + n] = a[((b * 14 + h + k) * 14 + (w + l)) * 32 + c];
    }
    __syncthreads();

    const int lane_o  = tid & 31;   // streaming: output capsule
    const int warp_nn = tid >> 5;   // streaming: n within chunk (0..3)
    const int obase = tid >> 4;     // stats role: o = obase + 8k (0..7 base)
    const int p3 = tid & 15;

    const u64* hm2_p = reinterpret_cast<const u64*>(smem + SM_HM2) + lane_o * 9;
    const u64* hsg_p = reinterpret_cast<const u64*>(smem + SM_HSG) + lane_o * 9;
    float* row1 = smem + SM_RED1 + warp_nn * 544 + lane_o * 17;  // bank-bijective over o
    float* row2 = smem + SM_RED2 + warp_nn * 544 + lane_o * 17;
    // coalesced W: lane o reads g_Wt[(n*4+y)*32 + o]; chunk advance = 4*4*32 ull2
    const ulonglong2* Wbase = g_Wt + (warp_nn << 7) + lane_o;

    for (int pass = 0; pass < 3; ++pass) {
        u64 s1p[8], s2p[8];
        #pragma unroll
        for (int j = 0; j < 8; ++j) { s1p[j] = 0ull; s2p[j] = 0ull; }
        float rs_reg = 0.f;

        // pass-invariant per-o constants, hoisted to registers
        float pre = 0.f;
        u64 hm2_r[8], hsg_r[8];
        if (pass > 0) {
            pre = smem[SM_PRE + lane_o];
            #pragma unroll
            for (int j = 0; j < 8; ++j) { hm2_r[j] = hm2_p[j]; hsg_r[j] = hsg_p[j]; }
        }

        // prefetch chunk 0's W rows (4 coalesced LDG.128)
        const ulonglong2* wp = Wbase;
        ulonglong2 wy0 = wp[0], wy1 = wp[32], wy2 = wp[64], wy3 = wp[96];

        #pragma unroll 1
        for (int ch = 0; ch < 72; ++ch) {
            const int n = ch * 4 + warp_nn;
            const float4* xv = reinterpret_cast<const float4*>(smem + SM_XP) + (n << 2);

            // V[n, lane_o, :] packed: vp[2x+hh] = (v[4x+2hh], v[4x+2hh+1])
            u64 vp[8];
            #pragma unroll
            for (int xx = 0; xx < 4; ++xx) {
                float4 xr = xv[xx];
                u64 b0 = pk2(xr.x, xr.x);
                u64 b1 = pk2(xr.y, xr.y);
                u64 b2 = pk2(xr.z, xr.z);
                u64 b3 = pk2(xr.w, xr.w);
                u64 lo = mul2(b0, wy0.x);
                lo = fma2(b1, wy1.x, lo);
                lo = fma2(b2, wy2.x, lo);
                lo = fma2(b3, wy3.x, lo);
                u64 hi = mul2(b0, wy0.y);
                hi = fma2(b1, wy1.y, hi);
                hi = fma2(b2, wy2.y, hi);
                hi = fma2(b3, wy3.y, hi);
                vp[xx * 2]     = lo;
                vp[xx * 2 + 1] = hi;
            }

            // wy dead: issue next chunk's W loads now (covered by logp/accum)
            if (ch < 71) {
                wp += 512;
                wy0 = wp[0]; wy1 = wp[32]; wy2 = wp[64]; wy3 = wp[96];
            }

            float Ra;
            if (pass == 0) {
                Ra = smem[SM_A + n] * 0.03125f;   // R uniform = 1/OC
            } else {
                // s = pre - (sum v^2*hsg + sum v*hm2); two parallel FMA chains
                u64 t2a = 0ull, t2b = 0ull;
                #pragma unroll
                for (int j = 0; j < 8; ++j) {
                    t2a = fma2(mul2(vp[j], vp[j]), hsg_r[j], t2a);
                    t2b = fma2(vp[j], hm2_r[j], t2b);
                }
                u64 t2 = add2(t2a, t2b);
                float tl, th; upk2(t2, tl, th);
                float s = pre - (tl + th);
                // softmax over o == softmax over warp lanes
                float m = warp_max_f32(s);           // single-op integer redux
                float e = __expf(s - m);
                float sum = e;
                #pragma unroll
                for (int off = 16; off; off >>= 1)
                    sum += __shfl_xor_sync(0xffffffffu, sum, off);
                Ra = __fdividef(e, sum) * smem[SM_A + n];
            }

            rs_reg += Ra;
            u64 Ra2 = pk2(Ra, Ra);
            #pragma unroll
            for (int j = 0; j < 8; ++j) {
                u64 rv = mul2(Ra2, vp[j]);
                s1p[j] = add2(s1p[j], rv);
                s2p[j] = fma2(rv, vp[j], s2p[j]);
            }
        }

        // ---- cross-warp reduction: STS partials to this warp's private row ----
        row1[16] = rs_reg;                   // Rs in the p=16 pad slot
        #pragma unroll
        for (int j = 0; j < 8; ++j) {
            float lo, hi;
            upk2(s1p[j], lo, hi);
            row1[2 * j] = lo; row1[2 * j + 1] = hi;
            upk2(s2p[j], lo, hi);
            row2[2 * j] = lo; row2[2 * j + 1] = hi;
        }
        __syncthreads();

        // ---- gather + stats: thread handles (obase + 8k, p3), k = 0..3 ----
        #pragma unroll
        for (int half = 0; half < 4; ++half) {
            const int o3 = obase + half * 8;
            float sS1 = 0.f, sS2 = 0.f, sRs = 0.f;
            {
                const float* g1 = smem + SM_RED1 + o3 * 17 + p3;
                const float* g2 = smem + SM_RED2 + o3 * 17 + p3;
                const float* gr = smem + SM_RED1 + o3 * 17 + 16;
                #pragma unroll
                for (int ww = 0; ww < 4; ++ww) {
                    sS1 += g1[ww * 544];
                    sS2 += g2[ww * 544];
                    sRs += gr[ww * 544];
                }
            }
            float Rsv   = sRs + EPSF;
            float invRs = 1.0f / Rsv;
            float mu    = sS1 * invRs;
            float sig2  = fmaxf(sS2 * invRs - mu * mu, 0.0f) + EPSF;
            float hsg   = __fdividef(0.5f, sig2);
            float sl    = __logf(sig2);
            float cc    = mu * mu * hsg;       // C contribution of this p
            #pragma unroll
            for (int off = 8; off; off >>= 1) { // reduce over 16 p-lanes
                sl += __shfl_xor_sync(0xffffffffu, sl, off);
                cc += __shfl_xor_sync(0xffffffffu, cc, off);
            }

            if (pass < 2) {
                smem[SM_HM2 + o3 * 18 + p3] = -2.0f * mu * hsg;  // -mu/sig2
                smem[SM_HSG + o3 * 18 + p3] = hsg;
                if (p3 == 0) {
                    float cost = Rsv * fmaf(0.5f, sl, 16.0f * bu_g[o3]);
                    float aout = 1.0f / (1.0f + __expf(cost - ba_g[o3]));
                    smem[SM_PRE + o3] = __logf(aout + EPSF) - 0.5f * sl - cc;
                }
            } else {
                out[pos * 512 + o3 * 16 + p3] = mu;
                if (p3 == 0) {
                    float cost = Rsv * fmaf(0.5f, sl, 16.0f * bu_g[o3]);
                    out[NPOS * 512 + pos * 32 + o3] =
                        1.0f / (1.0f + __expf(cost - ba_g[o3]));
                }
            }
        }
        if (pass < 2) __syncthreads();   // stats visible before next pass streams
    }
}

extern "C" void kernel_launch(void* const* d_in, const int* in_sizes, int n_in,
                              void* d_out, int out_size)
{
    (void)in_sizes; (void)n_in; (void)out_size;
    const float* x  = (const float*)d_in[0];
    const float* a  = (const float*)d_in[1];
    const float* W  = (const float*)d_in[2];
    const float* bu = (const float*)d_in[3];
    const float* ba = (const float*)d_in[4];
    transpose_W_kernel<<<144, 256>>>((const float4*)W);
    cudaFuncSetAttribute(caps_kernel,
                         cudaFuncAttributeMaxDynamicSharedMemorySize,
                         SM_TOT * (int)sizeof(float));
    caps_kernel<<<NPOS, 128, SM_TOT * sizeof(float)>>>(x, a, bu, ba, (float*)d_out);
}